// round 4
// baseline (speedup 1.0000x reference)
#include <cuda_runtime.h>
#include <cstdint>

#define BB 4
#define TT 2048
#define DD 1024
#define HH 16
#define DKK 64
#define SCALE_ 0.125f
#define EPS_LN_ 1e-5f
#define EPS_NORM_ 1e-8f

// within-8 column permutation: natural col c -> stored position perm8(c)
// order [0,4,1,5,2,6,3,7]; perm8(t)=2t, perm8(t+4)=2t+1 for t<4
__host__ __device__ __forceinline__ constexpr int perm8(int c) {
    return ((c & 3) << 1) | ((c >> 2) & 1);
}

// ---------------- scratch ----------------
__device__ float g_xn[BB * TT * DD];           // LN output, D-permuted
__device__ float g_q[BB * HH * TT * DKK];      // DK-permuted
__device__ float g_k[BB * HH * TT * DKK];      // DK-permuted
__device__ float g_vt[BB * HH * DKK * TT];     // V transposed [BH,DK,T], key-permuted
__device__ float g_ao[BB * TT * DD];           // attention out, D-permuted
__device__ float g_wc[4 * DD * DD];            // tf32 weights, D(k-dim)-permuted
__device__ unsigned char g_cmask[BB * TT];
__device__ int g_flags[3];

// ---------------- helpers ----------------
__device__ __forceinline__ unsigned f2tf(float x) {
    unsigned r;
    asm("cvt.rna.tf32.f32 %0, %1;" : "=r"(r) : "f"(x));
    return r;
}
__device__ __forceinline__ float f2tff(float x) { return __uint_as_float(f2tf(x)); }

__device__ __forceinline__ void mma_tf32(float* d, const unsigned* a,
                                         const unsigned* b, const float* c) {
    asm volatile(
        "mma.sync.aligned.m16n8k8.row.col.f32.tf32.tf32.f32 "
        "{%0,%1,%2,%3}, {%4,%5,%6,%7}, {%8,%9}, {%10,%11,%12,%13};"
        : "=f"(d[0]), "=f"(d[1]), "=f"(d[2]), "=f"(d[3])
        : "r"(a[0]), "r"(a[1]), "r"(a[2]), "r"(a[3]),
          "r"(b[0]), "r"(b[1]),
          "f"(c[0]), "f"(c[1]), "f"(c[2]), "f"(c[3]));
}
__device__ __forceinline__ void cp_async16(uint32_t saddr, const void* gptr) {
    asm volatile("cp.async.cg.shared.global [%0], [%1], 16;\n" :: "r"(saddr), "l"(gptr));
}
__device__ __forceinline__ void cp_commit() { asm volatile("cp.async.commit_group;\n" ::); }
__device__ __forceinline__ void cp_wait0()  { asm volatile("cp.async.wait_group 0;\n" ::); }
__device__ __forceinline__ uint32_t smem_u32(const void* p) {
    return (uint32_t)__cvta_generic_to_shared(p);
}

// ---------------- mask detection / canonicalization ----------------
__global__ void detect_mask_kernel(const unsigned char* __restrict__ m) {
    if (threadIdx.x == 0) { g_flags[0] = 0; g_flags[1] = 0; g_flags[2] = 0; }
    __syncthreads();
    int a = 0, bhi = 0, c = 0;
    for (int i = threadIdx.x; i < BB * TT; i += blockDim.x) {
        unsigned char v = m[i];
        if (v) {
            int r = i & 3;
            if (r == 0) a = 1;
            else if (r == 1) c = 1;
            else bhi = 1;
        }
    }
    if (a)   atomicOr(&g_flags[0], 1);
    if (bhi) atomicOr(&g_flags[1], 1);
    if (c)   atomicOr(&g_flags[2], 1);
}
__global__ void convert_mask_kernel(const void* __restrict__ m) {
    int i = blockIdx.x * blockDim.x + threadIdx.x;
    if (i >= BB * TT) return;
    int A = g_flags[0], Bf = g_flags[1], C = g_flags[2];
    unsigned char out;
    if (A && !Bf && !C)      out = (((const int*)m)[i] != 0);
    else if (!A && Bf)       out = (((const float*)m)[i] != 0.0f);
    else                     out = (((const unsigned char*)m)[i] != 0);
    g_cmask[i] = out;
}

// ---------------- weight conversion: tf32 round + D-perm ----------------
__global__ __launch_bounds__(256) void wconv_kernel(
    const float* __restrict__ w0, const float* __restrict__ w1,
    const float* __restrict__ w2, const float* __restrict__ w3) {
    const float* src = (blockIdx.y == 0) ? w0 : (blockIdx.y == 1) ? w1
                     : (blockIdx.y == 2) ? w2 : w3;
    float* dst = g_wc + (size_t)blockIdx.y * DD * DD;
    size_t i = ((size_t)blockIdx.x * 256 + threadIdx.x) * 4;
    float4 v = *(const float4*)&src[i];
    // elements i..i+3: stored at (i&~7) + 2j + ((i&4)>>2)
    size_t base = (i & ~(size_t)7) + ((i & 4) >> 2);
    dst[base + 0] = f2tff(v.x);
    dst[base + 2] = f2tff(v.y);
    dst[base + 4] = f2tff(v.z);
    dst[base + 6] = f2tff(v.w);
}

// ---------------- LayerNorm: tf32 round + D-perm ----------------
__global__ __launch_bounds__(256) void ln_kernel(
    const float* __restrict__ x, const float* __restrict__ g,
    const float* __restrict__ b) {
    __shared__ float red_s[8], red_ss[8];
    int row = blockIdx.x;
    int tid = threadIdx.x;
    const float* xr = x + (size_t)row * DD;
    float4 xv = *(const float4*)&xr[tid * 4];
    float s  = xv.x + xv.y + xv.z + xv.w;
    float ss = xv.x*xv.x + xv.y*xv.y + xv.z*xv.z + xv.w*xv.w;
    #pragma unroll
    for (int o = 16; o > 0; o >>= 1) {
        s  += __shfl_xor_sync(~0u, s, o);
        ss += __shfl_xor_sync(~0u, ss, o);
    }
    int warp = tid >> 5, lane = tid & 31;
    if (lane == 0) { red_s[warp] = s; red_ss[warp] = ss; }
    __syncthreads();
    if (warp == 0) {
        s  = (lane < 8) ? red_s[lane]  : 0.f;
        ss = (lane < 8) ? red_ss[lane] : 0.f;
        #pragma unroll
        for (int o = 4; o > 0; o >>= 1) {
            s  += __shfl_xor_sync(~0u, s, o);
            ss += __shfl_xor_sync(~0u, ss, o);
        }
        if (lane == 0) { red_s[0] = s; red_ss[0] = ss; }
    }
    __syncthreads();
    float mu  = red_s[0] * (1.0f / DD);
    float var = red_ss[0] * (1.0f / DD) - mu * mu;
    float inv = rsqrtf(var + EPS_LN_);
    float4 gv = *(const float4*)&g[tid * 4];
    float4 bv = *(const float4*)&b[tid * 4];
    float* dst = &g_xn[(size_t)row * DD + (tid & ~1) * 4 + (tid & 1)];
    dst[0] = f2tff((xv.x - mu) * inv * gv.x + bv.x);
    dst[2] = f2tff((xv.y - mu) * inv * gv.y + bv.y);
    dst[4] = f2tff((xv.z - mu) * inv * gv.z + bv.z);
    dst[6] = f2tff((xv.w - mu) * inv * gv.w + bv.w);
}

// ---------------- tf32 GEMM, cp.async double-buffered, perm frags ----------
#define GSTR 36
#define GTILE (128 * GSTR)
__global__ __launch_bounds__(256) void gemm_tc_kernel(
    const float* __restrict__ b0, const float* __restrict__ b1,
    const float* __restrict__ b2, int mode_base, float* __restrict__ dout) {
    extern __shared__ float gsm[];
    int mode = (mode_base == 3) ? 3 : (int)blockIdx.z;
    const float* W = g_wc + (size_t)mode * DD * DD;
    const float* bias = (mode == 1) ? b1 : (mode == 2) ? b2 : b0;
    const float* Aptr = (mode < 3) ? g_xn : g_ao;

    int tid  = threadIdx.x;
    int wid  = tid >> 5;
    int lane = tid & 31;
    int g = lane >> 2, t = lane & 3;
    int wm = (wid >> 2) * 64;
    int wn = (wid & 3) * 32;
    int m0 = blockIdx.y * 128;
    int n0 = blockIdx.x * 128;
    uint32_t sbase = smem_u32(gsm);

    float acc[4][4][4];
    #pragma unroll
    for (int i = 0; i < 4; i++)
        #pragma unroll
        for (int j = 0; j < 4; j++)
            #pragma unroll
            for (int e = 0; e < 4; e++) acc[i][j][e] = 0.f;

    auto load_stage = [&](int k0, int st) {
        #pragma unroll
        for (int p = 0; p < 4; p++) {
            int slot = tid + p * 256;
            int row  = slot >> 3;
            int col4 = (slot & 7) * 4;
            cp_async16(sbase + (uint32_t)((st * GTILE + row * GSTR + col4) * 4),
                       &Aptr[(size_t)(m0 + row) * DD + k0 + col4]);
            cp_async16(sbase + (uint32_t)(((2 + st) * GTILE + row * GSTR + col4) * 4),
                       &W[(size_t)(n0 + row) * DD + k0 + col4]);
        }
        cp_commit();
    };

    load_stage(0, 0);
    for (int it = 0; it < DD / 32; it++) {
        int cur = it & 1;
        cp_wait0();
        __syncthreads();
        if (it < DD / 32 - 1) load_stage((it + 1) * 32, cur ^ 1);
        const float* As = gsm + cur * GTILE;
        const float* Bs = gsm + (2 + cur) * GTILE;
        #pragma unroll
        for (int ks = 0; ks < 4; ks++) {
            int kc = ks * 8 + 2 * t;
            unsigned bf[4][2];
            #pragma unroll
            for (int n = 0; n < 4; n++) {
                float2 bb = *(const float2*)&Bs[(wn + n * 8 + g) * GSTR + kc];
                bf[n][0] = __float_as_uint(bb.x);
                bf[n][1] = __float_as_uint(bb.y);
            }
            #pragma unroll
            for (int mI = 0; mI < 4; mI++) {
                int rb = wm + mI * 16;
                float2 aA = *(const float2*)&As[(rb + g) * GSTR + kc];
                float2 aB = *(const float2*)&As[(rb + g + 8) * GSTR + kc];
                unsigned af[4] = {__float_as_uint(aA.x), __float_as_uint(aB.x),
                                  __float_as_uint(aA.y), __float_as_uint(aB.y)};
                #pragma unroll
                for (int n = 0; n < 4; n++)
                    mma_tf32(acc[mI][n], af, bf[n], acc[mI][n]);
            }
        }
    }

    #pragma unroll
    for (int mI = 0; mI < 4; mI++) {
        int r0 = m0 + wm + mI * 16 + g;           // r1 = r0+8, same batch tile
        int bi0 = r0 >> 11, t0 = r0 & (TT - 1);
        #pragma unroll
        for (int n = 0; n < 4; n++) {
            int e = n0 + wn + n * 8 + 2 * t;      // even col; pair (e, e+1)
            float bb0 = bias[e], bb1 = bias[e + 1];
            float v00 = acc[mI][n][0] + bb0, v01 = acc[mI][n][1] + bb1;
            float v10 = acc[mI][n][2] + bb0, v11 = acc[mI][n][3] + bb1;
            if (mode == 3) {
                float2 a = make_float2(v00 * 0.5f, v01 * 0.5f);
                float2 b = make_float2(v10 * 0.5f, v11 * 0.5f);
                *(float2*)&dout[(size_t)r0 * DD + e] = a;
                *(float2*)&dout[(size_t)(r0 + 8) * DD + e] = b;
            } else {
                int h = e >> 6, dk = e & 63;
                if (mode == 2) {
                    // V transposed: g_vt[(bh*DKK+dk)*TT + permuted key]
                    size_t vb = ((size_t)(bi0 * HH + h) * DKK + dk) * TT;
                    int tk0 = (t0 & ~7) | perm8(t0 & 7);
                    g_vt[vb + tk0]          = f2tff(v00);
                    g_vt[vb + TT + tk0]     = f2tff(v01);
                    g_vt[vb + tk0 + 8]      = f2tff(v10);
                    g_vt[vb + TT + tk0 + 8] = f2tff(v11);
                } else {
                    float* C = (mode == 0) ? g_q : g_k;
                    int dkp = (dk & ~7) | perm8(dk & 7);    // pair -> dkp, dkp+2
                    size_t base0 = (((size_t)(bi0 * HH + h) * TT + t0) << 6);
                    size_t base1 = base0 + (8 << 6);
                    C[base0 + dkp]     = v00;
                    C[base0 + dkp + 2] = v01;
                    C[base1 + dkp]     = v10;
                    C[base1 + dkp + 2] = v11;
                }
            }
        }
    }
}

// ---------------- L2 normalize (order-invariant over permuted rows) -------
__global__ __launch_bounds__(256) void l2norm_kernel() {
    int warp = (blockIdx.x * blockDim.x + threadIdx.x) >> 5;
    int lane = threadIdx.x & 31;
    float* base = (blockIdx.y == 0) ? g_q : g_k;
    float* p = base + (size_t)warp * DKK + lane * 2;
    float2 v = *(float2*)p;
    float ss = v.x * v.x + v.y * v.y;
    #pragma unroll
    for (int o = 16; o > 0; o >>= 1) ss += __shfl_xor_sync(~0u, ss, o);
    float n = sqrtf(ss);
    float inv = 1.0f / fmaxf(n, EPS_NORM_);
    v.x = f2tff(v.x * inv); v.y = f2tff(v.y * inv);
    *(float2*)p = v;
}

// ---------------- Flash attention: 8 warps, static softmax ----------------
#define ASTR 68
#define KT_F (64 * ASTR)                     // one K or VT tile in floats
#define P_OFF (4 * KT_F)                     // P buffer (128 x ASTR)
#define MSK_OFF (P_OFF + 128 * ASTR)
#define ASMEM (MSK_OFF * 4 + TT)             // bytes
__global__ __launch_bounds__(256, 2) void attn_tc_kernel() {
    extern __shared__ float asm_[];
    unsigned char* Msk = (unsigned char*)(asm_ + MSK_OFF);
    float* Ps = asm_ + P_OFF;

    int bh = blockIdx.y;
    int bi = bh >> 4;
    int h  = bh & 15;
    int qt = blockIdx.x;                      // 128-query tile
    int tid = threadIdx.x;
    int wid = tid >> 5;
    int lane = tid & 31;
    int g = lane >> 2, t = lane & 3;
    int wg = wid * 16;
    uint32_t sbase = smem_u32(asm_);

    if (tid < 128) ((uint4*)Msk)[tid] = ((const uint4*)(g_cmask + bi * TT))[tid];

    // resident Q fragments (DK-permuted storage -> float2 loads)
    unsigned qa[8][4];
    {
        const float* qp0 = g_q + (((size_t)(bh * TT + qt * 128 + wg + g)) << 6);
        const float* qp1 = qp0 + (8 << 6);
        #pragma unroll
        for (int ks = 0; ks < 8; ks++) {
            float2 qA = *(const float2*)&qp0[ks * 8 + 2 * t];
            float2 qB = *(const float2*)&qp1[ks * 8 + 2 * t];
            qa[ks][0] = __float_as_uint(qA.x);
            qa[ks][1] = __float_as_uint(qB.x);
            qa[ks][2] = __float_as_uint(qA.y);
            qa[ks][3] = __float_as_uint(qB.y);
        }
    }

    float o_acc[8][4];
    #pragma unroll
    for (int n = 0; n < 8; n++)
        #pragma unroll
        for (int e = 0; e < 4; e++) o_acc[n][e] = 0.f;
    float psum0 = 0.f, psum1 = 0.f;

    const float* kbase  = g_k  + (((size_t)bh * TT) << 6);
    const float* vtbase = g_vt + (size_t)bh * DKK * TT;

    auto load_kv = [&](int kt, int st) {
        const float* kb = kbase + (((size_t)kt * 64) << 6);
        const float* vb = vtbase + kt * 64;
        #pragma unroll
        for (int p = 0; p < 4; p++) {
            int slot = tid + p * 256;
            int row  = slot >> 4;
            int col4 = (slot & 15) * 4;
            cp_async16(sbase + (uint32_t)((st * KT_F + row * ASTR + col4) * 4),
                       &kb[(row << 6) + col4]);
            cp_async16(sbase + (uint32_t)(((2 + st) * KT_F + row * ASTR + col4) * 4),
                       &vb[(size_t)row * TT + col4]);
        }
        cp_commit();
    };

    load_kv(0, 0);
    for (int kt = 0; kt < TT / 64; kt++) {
        int cur = kt & 1;
        cp_wait0();
        __syncthreads();
        if (kt < TT / 64 - 1) load_kv(kt + 1, cur ^ 1);

        const float* Ks  = asm_ + cur * KT_F;
        const float* VsT = asm_ + (2 + cur) * KT_F;

        // S = Q.K^T (16 x 64 per warp)
        float sc[8][4];
        #pragma unroll
        for (int n = 0; n < 8; n++)
            #pragma unroll
            for (int e = 0; e < 4; e++) sc[n][e] = 0.f;
        #pragma unroll
        for (int ks = 0; ks < 8; ks++) {
            int kc = ks * 8 + 2 * t;
            #pragma unroll
            for (int n = 0; n < 8; n++) {
                float2 kb2 = *(const float2*)&Ks[(n * 8 + g) * ASTR + kc];
                unsigned bf[2] = {__float_as_uint(kb2.x), __float_as_uint(kb2.y)};
                mma_tf32(sc[n], qa[ks], bf, sc[n]);
            }
        }

        // static softmax weights; masked -> 0
        const unsigned char* mrow = Msk + kt * 64;
        #pragma unroll
        for (int n = 0; n < 8; n++) {
            bool mk0 = mrow[n * 8 + 2 * t] != 0;
            bool mk1 = mrow[n * 8 + 2 * t + 1] != 0;
            sc[n][0] = mk0 ? 0.f : __expf(sc[n][0] * SCALE_);
            sc[n][1] = mk1 ? 0.f : __expf(sc[n][1] * SCALE_);
            sc[n][2] = mk0 ? 0.f : __expf(sc[n][2] * SCALE_);
            sc[n][3] = mk1 ? 0.f : __expf(sc[n][3] * SCALE_);
            psum0 += sc[n][0] + sc[n][1];
            psum1 += sc[n][2] + sc[n][3];
        }

        // P -> warp-private smem, key-permuted cols (no block barrier!)
        #pragma unroll
        for (int n = 0; n < 8; n++) {
            int p0 = n * 8 + perm8(2 * t);        // pair -> p0, p0+2
            Ps[(wg + g) * ASTR + p0]         = f2tff(sc[n][0]);
            Ps[(wg + g) * ASTR + p0 + 2]     = f2tff(sc[n][1]);
            Ps[(wg + g + 8) * ASTR + p0]     = f2tff(sc[n][2]);
            Ps[(wg + g + 8) * ASTR + p0 + 2] = f2tff(sc[n][3]);
        }
        __syncwarp();

        // O += P.V  (VT rows = dk, key cols permuted to match P)
        #pragma unroll
        for (int ks = 0; ks < 8; ks++) {
            int kc = ks * 8 + 2 * t;
            float2 pA = *(const float2*)&Ps[(wg + g) * ASTR + kc];
            float2 pB = *(const float2*)&Ps[(wg + g + 8) * ASTR + kc];
            unsigned pa[4] = {__float_as_uint(pA.x), __float_as_uint(pB.x),
                              __float_as_uint(pA.y), __float_as_uint(pB.y)};
            #pragma unroll
            for (int n = 0; n < 8; n++) {
                float2 vb2 = *(const float2*)&VsT[(n * 8 + g) * ASTR + kc];
                unsigned bf[2] = {__float_as_uint(vb2.x), __float_as_uint(vb2.y)};
                mma_tf32(o_acc[n], pa, bf, o_acc[n]);
            }
        }
        __syncwarp();   // P reads done before next tile's P writes
    }

    psum0 += __shfl_xor_sync(~0u, psum0, 1);
    psum0 += __shfl_xor_sync(~0u, psum0, 2);
    psum1 += __shfl_xor_sync(~0u, psum1, 1);
    psum1 += __shfl_xor_sync(~0u, psum1, 2);
    float inv0 = 1.0f / psum0;
    float inv1 = 1.0f / psum1;
    int tq0 = qt * 128 + wg + g;
    float* ob0 = g_ao + ((size_t)bi * TT + tq0) * DD + h * 64;
    float* ob1 = ob0 + 8 * DD;
    #pragma unroll
    for (int n = 0; n < 8; n++) {
        int p0 = n * 8 + perm8(2 * t);            // D-perm for O-GEMM
        ob0[p0]     = f2tff(o_acc[n][0] * inv0);
        ob0[p0 + 2] = f2tff(o_acc[n][1] * inv0);
        ob1[p0]     = f2tff(o_acc[n][2] * inv1);
        ob1[p0 + 2] = f2tff(o_acc[n][3] * inv1);
    }
}

// ---------------- launch ----------------
extern "C" void kernel_launch(void* const* d_in, const int* in_sizes, int n_in,
                              void* d_out, int out_size) {
    const float* x    = (const float*)d_in[0];
    const void*  mask = d_in[1];
    const float* wq = (const float*)d_in[2];
    const float* bq = (const float*)d_in[3];
    const float* wk = (const float*)d_in[4];
    const float* bk = (const float*)d_in[5];
    const float* wv = (const float*)d_in[6];
    const float* bv = (const float*)d_in[7];
    const float* wo = (const float*)d_in[8];
    const float* bo = (const float*)d_in[9];
    const float* ln_g = (const float*)d_in[10];
    const float* ln_b = (const float*)d_in[11];
    float* out = (float*)d_out;

    const int gemm_smem = 4 * GTILE * 4;          // 73728 B
    const int attn_smem = ASMEM;                  // 106496 B
    cudaFuncSetAttribute(gemm_tc_kernel,
        cudaFuncAttributeMaxDynamicSharedMemorySize, gemm_smem);
    cudaFuncSetAttribute(attn_tc_kernel,
        cudaFuncAttributeMaxDynamicSharedMemorySize, attn_smem);

    detect_mask_kernel<<<1, 256>>>((const unsigned char*)mask);
    convert_mask_kernel<<<(BB * TT + 255) / 256, 256>>>(mask);
    wconv_kernel<<<dim3(DD * DD / 1024, 4), 256>>>(wq, wk, wv, wo);
    ln_kernel<<<BB * TT, 256>>>(x, ln_g, ln_b);

    dim3 qkv_grid(DD / 128, (BB * TT) / 128, 3);
    gemm_tc_kernel<<<qkv_grid, 256, gemm_smem>>>(bq, bk, bv, 0, nullptr);

    dim3 l2grid((BB * HH * TT) / 8, 2);
    l2norm_kernel<<<l2grid, 256>>>();

    dim3 agrid(TT / 128, BB * HH);                // (16, 64)
    attn_tc_kernel<<<agrid, 256, attn_smem>>>();

    dim3 ogrid(DD / 128, (BB * TT) / 128, 1);
    gemm_tc_kernel<<<ogrid, 256, gemm_smem>>>(bo, nullptr, nullptr, 3, out);
}

// round 5
// speedup vs baseline: 1.3765x; 1.3765x over previous
#include <cuda_runtime.h>
#include <cstdint>

#define BB 4
#define TT 2048
#define DD 1024
#define HH 16
#define DKK 64
#define SCALE_ 0.125f
#define EPS_LN_ 1e-5f
#define EPS_NORM_ 1e-8f

// within-8 column permutation: natural col c -> stored position perm8(c)
// order [0,4,1,5,2,6,3,7]; perm8(t)=2t, perm8(t+4)=2t+1 for t<4
__host__ __device__ __forceinline__ constexpr int perm8(int c) {
    return ((c & 3) << 1) | ((c >> 2) & 1);
}

// ---------------- scratch ----------------
__device__ float g_xn[BB * TT * DD];           // LN output, D-permuted
__device__ float g_q[BB * HH * TT * DKK];      // DK-permuted
__device__ float g_k[BB * HH * TT * DKK];      // DK-permuted
__device__ float g_v[BB * HH * TT * DKK];      // natural [B,H,T,DK]
__device__ float g_ao[BB * TT * DD];           // attention out, D-permuted
__device__ float g_wc[4 * DD * DD];            // tf32 weights, k-dim permuted
__device__ unsigned char g_cmask[BB * TT];
__device__ int g_flags[3];

// ---------------- helpers ----------------
__device__ __forceinline__ unsigned f2tf(float x) {
    unsigned r;
    asm("cvt.rna.tf32.f32 %0, %1;" : "=r"(r) : "f"(x));
    return r;
}
__device__ __forceinline__ float f2tff(float x) { return __uint_as_float(f2tf(x)); }

__device__ __forceinline__ void mma_tf32(float* d, const unsigned* a,
                                         const unsigned* b, const float* c) {
    asm volatile(
        "mma.sync.aligned.m16n8k8.row.col.f32.tf32.tf32.f32 "
        "{%0,%1,%2,%3}, {%4,%5,%6,%7}, {%8,%9}, {%10,%11,%12,%13};"
        : "=f"(d[0]), "=f"(d[1]), "=f"(d[2]), "=f"(d[3])
        : "r"(a[0]), "r"(a[1]), "r"(a[2]), "r"(a[3]),
          "r"(b[0]), "r"(b[1]),
          "f"(c[0]), "f"(c[1]), "f"(c[2]), "f"(c[3]));
}
__device__ __forceinline__ void cp_async16(uint32_t saddr, const void* gptr) {
    asm volatile("cp.async.cg.shared.global [%0], [%1], 16;\n" :: "r"(saddr), "l"(gptr));
}
__device__ __forceinline__ void cp_commit() { asm volatile("cp.async.commit_group;\n" ::); }
__device__ __forceinline__ void cp_wait0()  { asm volatile("cp.async.wait_group 0;\n" ::); }
__device__ __forceinline__ uint32_t smem_u32(const void* p) {
    return (uint32_t)__cvta_generic_to_shared(p);
}

// ---------------- mask detection / canonicalization ----------------
__global__ void detect_mask_kernel(const unsigned char* __restrict__ m) {
    if (threadIdx.x == 0) { g_flags[0] = 0; g_flags[1] = 0; g_flags[2] = 0; }
    __syncthreads();
    int a = 0, bhi = 0, c = 0;
    for (int i = threadIdx.x; i < BB * TT; i += blockDim.x) {
        unsigned char v = m[i];
        if (v) {
            int r = i & 3;
            if (r == 0) a = 1;
            else if (r == 1) c = 1;
            else bhi = 1;
        }
    }
    if (a)   atomicOr(&g_flags[0], 1);
    if (bhi) atomicOr(&g_flags[1], 1);
    if (c)   atomicOr(&g_flags[2], 1);
}
__global__ void convert_mask_kernel(const void* __restrict__ m) {
    int i = blockIdx.x * blockDim.x + threadIdx.x;
    if (i >= BB * TT) return;
    int A = g_flags[0], Bf = g_flags[1], C = g_flags[2];
    unsigned char out;
    if (A && !Bf && !C)      out = (((const int*)m)[i] != 0);
    else if (!A && Bf)       out = (((const float*)m)[i] != 0.0f);
    else                     out = (((const unsigned char*)m)[i] != 0);
    g_cmask[i] = out;
}

// ---------------- weight conversion: tf32 round + k-dim perm ----------------
__global__ __launch_bounds__(256) void wconv_kernel(
    const float* __restrict__ w0, const float* __restrict__ w1,
    const float* __restrict__ w2, const float* __restrict__ w3) {
    const float* src = (blockIdx.y == 0) ? w0 : (blockIdx.y == 1) ? w1
                     : (blockIdx.y == 2) ? w2 : w3;
    float* dst = g_wc + (size_t)blockIdx.y * DD * DD;
    size_t i = ((size_t)blockIdx.x * 256 + threadIdx.x) * 4;
    float4 v = *(const float4*)&src[i];
    size_t base = (i & ~(size_t)7) + ((i & 4) >> 2);
    dst[base + 0] = f2tff(v.x);
    dst[base + 2] = f2tff(v.y);
    dst[base + 4] = f2tff(v.z);
    dst[base + 6] = f2tff(v.w);
}

// ---------------- LayerNorm: tf32 round + D-perm ----------------
__global__ __launch_bounds__(256) void ln_kernel(
    const float* __restrict__ x, const float* __restrict__ g,
    const float* __restrict__ b) {
    __shared__ float red_s[8], red_ss[8];
    int row = blockIdx.x;
    int tid = threadIdx.x;
    const float* xr = x + (size_t)row * DD;
    float4 xv = *(const float4*)&xr[tid * 4];
    float s  = xv.x + xv.y + xv.z + xv.w;
    float ss = xv.x*xv.x + xv.y*xv.y + xv.z*xv.z + xv.w*xv.w;
    #pragma unroll
    for (int o = 16; o > 0; o >>= 1) {
        s  += __shfl_xor_sync(~0u, s, o);
        ss += __shfl_xor_sync(~0u, ss, o);
    }
    int warp = tid >> 5, lane = tid & 31;
    if (lane == 0) { red_s[warp] = s; red_ss[warp] = ss; }
    __syncthreads();
    if (warp == 0) {
        s  = (lane < 8) ? red_s[lane]  : 0.f;
        ss = (lane < 8) ? red_ss[lane] : 0.f;
        #pragma unroll
        for (int o = 4; o > 0; o >>= 1) {
            s  += __shfl_xor_sync(~0u, s, o);
            ss += __shfl_xor_sync(~0u, ss, o);
        }
        if (lane == 0) { red_s[0] = s; red_ss[0] = ss; }
    }
    __syncthreads();
    float mu  = red_s[0] * (1.0f / DD);
    float var = red_ss[0] * (1.0f / DD) - mu * mu;
    float inv = rsqrtf(var + EPS_LN_);
    float4 gv = *(const float4*)&g[tid * 4];
    float4 bv = *(const float4*)&b[tid * 4];
    float* dst = &g_xn[(size_t)row * DD + (tid & ~1) * 4 + (tid & 1)];
    dst[0] = f2tff((xv.x - mu) * inv * gv.x + bv.x);
    dst[2] = f2tff((xv.y - mu) * inv * gv.y + bv.y);
    dst[4] = f2tff((xv.z - mu) * inv * gv.z + bv.z);
    dst[6] = f2tff((xv.w - mu) * inv * gv.w + bv.w);
}

// ---------------- tf32 GEMM, cp.async double-buffered, float2 frags --------
#define GSTR 40
#define GTILE (128 * GSTR)
__global__ __launch_bounds__(256) void gemm_tc_kernel(
    const float* __restrict__ b0, const float* __restrict__ b1,
    const float* __restrict__ b2, int mode_base, float* __restrict__ dout) {
    extern __shared__ float gsm[];
    int mode = (mode_base == 3) ? 3 : (int)blockIdx.z;
    const float* W = g_wc + (size_t)mode * DD * DD;
    const float* bias = (mode == 1) ? b1 : (mode == 2) ? b2 : b0;
    const float* Aptr = (mode < 3) ? g_xn : g_ao;

    int tid  = threadIdx.x;
    int wid  = tid >> 5;
    int lane = tid & 31;
    int g = lane >> 2, t = lane & 3;
    int wm = (wid >> 2) * 64;
    int wn = (wid & 3) * 32;
    int m0 = blockIdx.y * 128;
    int n0 = blockIdx.x * 128;
    uint32_t sbase = smem_u32(gsm);

    float acc[4][4][4];
    #pragma unroll
    for (int i = 0; i < 4; i++)
        #pragma unroll
        for (int j = 0; j < 4; j++)
            #pragma unroll
            for (int e = 0; e < 4; e++) acc[i][j][e] = 0.f;

    auto load_stage = [&](int k0, int st) {
        #pragma unroll
        for (int p = 0; p < 4; p++) {
            int slot = tid + p * 256;
            int row  = slot >> 3;
            int col4 = (slot & 7) * 4;
            cp_async16(sbase + (uint32_t)((st * GTILE + row * GSTR + col4) * 4),
                       &Aptr[(size_t)(m0 + row) * DD + k0 + col4]);
            cp_async16(sbase + (uint32_t)(((2 + st) * GTILE + row * GSTR + col4) * 4),
                       &W[(size_t)(n0 + row) * DD + k0 + col4]);
        }
        cp_commit();
    };

    load_stage(0, 0);
    for (int it = 0; it < DD / 32; it++) {
        int cur = it & 1;
        cp_wait0();
        __syncthreads();
        if (it < DD / 32 - 1) load_stage((it + 1) * 32, cur ^ 1);
        const float* As = gsm + cur * GTILE;
        const float* Bs = gsm + (2 + cur) * GTILE;
        #pragma unroll
        for (int ks = 0; ks < 4; ks++) {
            int kc = ks * 8 + 2 * t;               // permuted {t, t+4} adjacent
            unsigned bf[4][2];
            #pragma unroll
            for (int n = 0; n < 4; n++) {
                float2 bb = *(const float2*)&Bs[(wn + n * 8 + g) * GSTR + kc];
                bf[n][0] = __float_as_uint(bb.x);
                bf[n][1] = __float_as_uint(bb.y);
            }
            #pragma unroll
            for (int mI = 0; mI < 4; mI++) {
                int rb = wm + mI * 16;
                float2 aA = *(const float2*)&As[(rb + g) * GSTR + kc];
                float2 aB = *(const float2*)&As[(rb + g + 8) * GSTR + kc];
                unsigned af[4] = {__float_as_uint(aA.x), __float_as_uint(aB.x),
                                  __float_as_uint(aA.y), __float_as_uint(aB.y)};
                #pragma unroll
                for (int n = 0; n < 4; n++)
                    mma_tf32(acc[mI][n], af, bf[n], acc[mI][n]);
            }
        }
    }

    #pragma unroll
    for (int mI = 0; mI < 4; mI++) {
        int r0 = m0 + wm + mI * 16 + g;
        int bi0 = r0 >> 11, t0 = r0 & (TT - 1);
        #pragma unroll
        for (int n = 0; n < 4; n++) {
            int e = n0 + wn + n * 8 + 2 * t;       // natural pair (e, e+1)
            float bb0 = bias[e], bb1 = bias[e + 1];
            float v00 = acc[mI][n][0] + bb0, v01 = acc[mI][n][1] + bb1;
            float v10 = acc[mI][n][2] + bb0, v11 = acc[mI][n][3] + bb1;
            if (mode == 3) {
                *(float2*)&dout[(size_t)r0 * DD + e] =
                    make_float2(v00 * 0.5f, v01 * 0.5f);
                *(float2*)&dout[(size_t)(r0 + 8) * DD + e] =
                    make_float2(v10 * 0.5f, v11 * 0.5f);
            } else {
                int h = e >> 6, dk = e & 63;
                size_t base0 = (((size_t)(bi0 * HH + h) * TT + t0) << 6);
                size_t base1 = base0 + (8 << 6);
                if (mode == 2) {                   // V natural, tf32-rounded
                    *(float2*)&g_v[base0 + dk] = make_float2(f2tff(v00), f2tff(v01));
                    *(float2*)&g_v[base1 + dk] = make_float2(f2tff(v10), f2tff(v11));
                } else {                           // Q,K DK-permuted scatter
                    float* C = (mode == 0) ? g_q : g_k;
                    int dkp = (dk & ~7) | perm8(dk & 7);   // pair -> dkp, dkp+2
                    C[base0 + dkp]     = v00;
                    C[base0 + dkp + 2] = v01;
                    C[base1 + dkp]     = v10;
                    C[base1 + dkp + 2] = v11;
                }
            }
        }
    }
}

// ---------------- L2 normalize (order-invariant over permuted rows) -------
__global__ __launch_bounds__(256) void l2norm_kernel() {
    int warp = (blockIdx.x * blockDim.x + threadIdx.x) >> 5;
    int lane = threadIdx.x & 31;
    float* base = (blockIdx.y == 0) ? g_q : g_k;
    float* p = base + (size_t)warp * DKK + lane * 2;
    float2 v = *(float2*)p;
    float ss = v.x * v.x + v.y * v.y;
    #pragma unroll
    for (int o = 16; o > 0; o >>= 1) ss += __shfl_xor_sync(~0u, ss, o);
    float n = sqrtf(ss);
    float inv = 1.0f / fmaxf(n, EPS_NORM_);
    v.x = f2tff(v.x * inv); v.y = f2tff(v.y * inv);
    *(float2*)p = v;
}

// ---------------- Flash attention: static softmax, R3 structure ------------
// ASTR=72: 8-row stride = 8 banks -> conflict-free float2 K-frags AND
// conflict-free PV V-column loads (R3's ASTR=68 had 2-way conflicts there).
#define ASTR 72
#define ATILE (64 * ASTR)
#define ASMEM (4 * ATILE * 4 + TT)   // bytes: K0 K1 V0 V1 + mask row
__global__ __launch_bounds__(128) void attn_tc_kernel() {
    extern __shared__ float asm_[];
    unsigned char* Msk = (unsigned char*)(asm_ + 4 * ATILE);

    int bh = blockIdx.y;
    int bi = bh >> 4;
    int h  = bh & 15;
    int qt = blockIdx.x;
    int tid = threadIdx.x;
    int wid = tid >> 5;
    int lane = tid & 31;
    int g = lane >> 2, t = lane & 3;
    int wg = wid * 16;
    uint32_t sbase = smem_u32(asm_);

    ((uint4*)Msk)[tid] = ((const uint4*)(g_cmask + bi * TT))[tid];

    // resident Q fragments (DK-permuted storage -> float2 loads)
    unsigned qa[8][4];
    {
        const float* qp0 = g_q + (((size_t)(bh * TT + qt * 64 + wg + g)) << 6);
        const float* qp1 = qp0 + (8 << 6);
        #pragma unroll
        for (int ks = 0; ks < 8; ks++) {
            float2 qA = *(const float2*)&qp0[ks * 8 + 2 * t];
            float2 qB = *(const float2*)&qp1[ks * 8 + 2 * t];
            qa[ks][0] = __float_as_uint(qA.x);
            qa[ks][1] = __float_as_uint(qB.x);
            qa[ks][2] = __float_as_uint(qA.y);
            qa[ks][3] = __float_as_uint(qB.y);
        }
    }

    float o_acc[8][4];
    #pragma unroll
    for (int n = 0; n < 8; n++)
        #pragma unroll
        for (int e = 0; e < 4; e++) o_acc[n][e] = 0.f;
    float psum0 = 0.f, psum1 = 0.f;

    const float* kbase = g_k + (((size_t)bh * TT) << 6);
    const float* vbase = g_v + (((size_t)bh * TT) << 6);

    auto load_kv = [&](int kt, int st) {
        const float* kb = kbase + ((size_t)(kt * 64) << 6);
        const float* vb = vbase + ((size_t)(kt * 64) << 6);
        #pragma unroll
        for (int p = 0; p < 8; p++) {
            int slot = tid + p * 128;
            int row  = slot >> 4;
            int col4 = (slot & 15) * 4;
            cp_async16(sbase + (uint32_t)((st * ATILE + row * ASTR + col4) * 4),
                       &kb[(row << 6) + col4]);
            cp_async16(sbase + (uint32_t)(((2 + st) * ATILE + row * ASTR + col4) * 4),
                       &vb[(row << 6) + col4]);
        }
        cp_commit();
    };

    load_kv(0, 0);
    for (int kt = 0; kt < TT / 64; kt++) {
        int cur = kt & 1;
        cp_wait0();
        __syncthreads();
        if (kt < TT / 64 - 1) load_kv(kt + 1, cur ^ 1);

        float* Ks = asm_ + cur * ATILE;
        float* Vs = asm_ + (2 + cur) * ATILE;

        // S = Q.K^T (float2 b-frags from DK-permuted K)
        float sc[8][4];
        #pragma unroll
        for (int n = 0; n < 8; n++)
            #pragma unroll
            for (int e = 0; e < 4; e++) sc[n][e] = 0.f;
        #pragma unroll
        for (int ks = 0; ks < 8; ks++) {
            int kc = ks * 8 + 2 * t;
            #pragma unroll
            for (int n = 0; n < 8; n++) {
                float2 kb2 = *(const float2*)&Ks[(n * 8 + g) * ASTR + kc];
                unsigned bf[2] = {__float_as_uint(kb2.x), __float_as_uint(kb2.y)};
                mma_tf32(sc[n], qa[ks], bf, sc[n]);
            }
        }

        // static softmax weights; masked -> 0
        const unsigned char* mrow = Msk + kt * 64;
        #pragma unroll
        for (int n = 0; n < 8; n++) {
            bool mk0 = mrow[n * 8 + 2 * t] != 0;
            bool mk1 = mrow[n * 8 + 2 * t + 1] != 0;
            sc[n][0] = mk0 ? 0.f : __expf(sc[n][0] * SCALE_);
            sc[n][1] = mk1 ? 0.f : __expf(sc[n][1] * SCALE_);
            sc[n][2] = mk0 ? 0.f : __expf(sc[n][2] * SCALE_);
            sc[n][3] = mk1 ? 0.f : __expf(sc[n][3] * SCALE_);
            psum0 += sc[n][0] + sc[n][1];
            psum1 += sc[n][2] + sc[n][3];
        }

        __syncthreads();                 // all warps done reading K[cur]
        // P (tf32) aliased over K[cur], natural key columns
        #pragma unroll
        for (int n = 0; n < 8; n++) {
            int c = n * 8 + 2 * t;
            *(float2*)&Ks[(wg + g) * ASTR + c] =
                make_float2(f2tff(sc[n][0]), f2tff(sc[n][1]));
            *(float2*)&Ks[(wg + g + 8) * ASTR + c] =
                make_float2(f2tff(sc[n][2]), f2tff(sc[n][3]));
        }
        __syncwarp();

        // O += P.V
        #pragma unroll
        for (int ks = 0; ks < 8; ks++) {
            int kc = ks * 8;
            unsigned pa[4];
            pa[0] = __float_as_uint(Ks[(wg + g) * ASTR + kc + t]);
            pa[1] = __float_as_uint(Ks[(wg + g + 8) * ASTR + kc + t]);
            pa[2] = __float_as_uint(Ks[(wg + g) * ASTR + kc + t + 4]);
            pa[3] = __float_as_uint(Ks[(wg + g + 8) * ASTR + kc + t + 4]);
            #pragma unroll
            for (int n = 0; n < 8; n++) {
                unsigned bf[2];
                bf[0] = __float_as_uint(Vs[(kc + t) * ASTR + n * 8 + g]);
                bf[1] = __float_as_uint(Vs[(kc + t + 4) * ASTR + n * 8 + g]);
                mma_tf32(o_acc[n], pa, bf, o_acc[n]);
            }
        }
    }

    psum0 += __shfl_xor_sync(~0u, psum0, 1);
    psum0 += __shfl_xor_sync(~0u, psum0, 2);
    psum1 += __shfl_xor_sync(~0u, psum1, 1);
    psum1 += __shfl_xor_sync(~0u, psum1, 2);
    float inv0 = 1.0f / psum0;
    float inv1 = 1.0f / psum1;
    int tq0 = qt * 64 + wg + g;
    float* ob0 = g_ao + ((size_t)bi * TT + tq0) * DD + h * 64;
    float* ob1 = ob0 + 8 * DD;
    #pragma unroll
    for (int n = 0; n < 8; n++) {
        int p0 = n * 8 + perm8(2 * t);            // D-perm for O-GEMM feed
        ob0[p0]     = f2tff(o_acc[n][0] * inv0);
        ob0[p0 + 2] = f2tff(o_acc[n][1] * inv0);
        ob1[p0]     = f2tff(o_acc[n][2] * inv1);
        ob1[p0 + 2] = f2tff(o_acc[n][3] * inv1);
    }
}

// ---------------- launch ----------------
extern "C" void kernel_launch(void* const* d_in, const int* in_sizes, int n_in,
                              void* d_out, int out_size) {
    const float* x    = (const float*)d_in[0];
    const void*  mask = d_in[1];
    const float* wq = (const float*)d_in[2];
    const float* bq = (const float*)d_in[3];
    const float* wk = (const float*)d_in[4];
    const float* bk = (const float*)d_in[5];
    const float* wv = (const float*)d_in[6];
    const float* bv = (const float*)d_in[7];
    const float* wo = (const float*)d_in[8];
    const float* bo = (const float*)d_in[9];
    const float* ln_g = (const float*)d_in[10];
    const float* ln_b = (const float*)d_in[11];
    float* out = (float*)d_out;

    const int gemm_smem = 4 * GTILE * 4;          // 81920 B
    const int attn_smem = ASMEM;                  // 75776 B
    cudaFuncSetAttribute(gemm_tc_kernel,
        cudaFuncAttributeMaxDynamicSharedMemorySize, gemm_smem);
    cudaFuncSetAttribute(attn_tc_kernel,
        cudaFuncAttributeMaxDynamicSharedMemorySize, attn_smem);

    detect_mask_kernel<<<1, 256>>>((const unsigned char*)mask);
    convert_mask_kernel<<<(BB * TT + 255) / 256, 256>>>(mask);
    wconv_kernel<<<dim3(DD * DD / 1024, 4), 256>>>(wq, wk, wv, wo);
    ln_kernel<<<BB * TT, 256>>>(x, ln_g, ln_b);

    dim3 qkv_grid(DD / 128, (BB * TT) / 128, 3);
    gemm_tc_kernel<<<qkv_grid, 256, gemm_smem>>>(bq, bk, bv, 0, nullptr);

    dim3 l2grid((BB * HH * TT) / 8, 2);
    l2norm_kernel<<<l2grid, 256>>>();

    dim3 agrid(TT / 64, BB * HH);                 // (32, 64)
    attn_tc_kernel<<<agrid, 128, attn_smem>>>();

    dim3 ogrid(DD / 128, (BB * TT) / 128, 1);
    gemm_tc_kernel<<<ogrid, 256, gemm_smem>>>(bo, nullptr, nullptr, 3, out);
}